// round 12
// baseline (speedup 1.0000x reference)
#include <cuda_runtime.h>

typedef unsigned long long ull;

#define D_IN   992
#define HID    32
#define W1     6
#define NB     12
#define KC     16               // k per tile
#define RPB    256              // rows per block
#define NTHR   128
#define NTILES 62               // 62*16 = 992
#define ASTR   388              // words per k-row of As (padded-block layout)
#define WSTR   36               // words per k-row of Ws

// dynamic smem layout (bytes)
#define ABYTES   (KC * ASTR * 4)          // 24832
#define WBYTES   (KC * WSTR * 4)          // 2304
#define BUFBYTES (ABYTES + WBYTES)        // 27136
#define PRM_OFF  (2 * BUFBYTES)           // 54272
#define SMEM_SZ  (PRM_OFF + 10560)        // 64832

__device__ __forceinline__ ull ffma2(ull a, ull b, ull c) {
    ull d;
    asm("fma.rn.f32x2 %0, %1, %2, %3;" : "=l"(d) : "l"(a), "l"(b), "l"(c));
    return d;
}
__device__ __forceinline__ ull dup64(float a) {
    ull d;
    asm("mov.b64 %0, {%1, %1};" : "=l"(d) : "f"(a));
    return d;
}

// padded-block row map: 8-row groups + 4-word pad.
__device__ __forceinline__ int Pmap(int r) { return r + ((r >> 3) << 2); }

// Compact degree-4 uniform B-spline: 5 nonzero values + masked clamped indices.
__device__ __forceinline__ void basis5m(float x, float Bv[5], int ix[5]) {
    float u  = (x + 2.0f) * 4.0f;
    float fj = floorf(u);
    int   j0 = (int)fj;
    float s  = u - fj;
    float B0, B1, B2, B3, B4;
    B1 = s;  B0 = 1.0f - s;
    B2 = 0.5f * (s * B1);
    B1 = 0.5f * ((s + 1.0f) * B0 + (2.0f - s) * B1);
    B0 = 0.5f * ((1.0f - s) * B0);
    const float i3 = (1.0f / 3.0f);
    B3 = i3 * (s * B2);
    B2 = i3 * ((s + 1.0f) * B1 + (3.0f - s) * B2);
    B1 = i3 * ((s + 2.0f) * B0 + (2.0f - s) * B1);
    B0 = i3 * ((1.0f - s) * B0);
    B4 = 0.25f * (s * B3);
    B3 = 0.25f * ((s + 1.0f) * B2 + (4.0f - s) * B3);
    B2 = 0.25f * ((s + 2.0f) * B1 + (3.0f - s) * B2);
    B1 = 0.25f * ((s + 3.0f) * B0 + (2.0f - s) * B1);
    B0 = 0.25f * ((1.0f - s) * B0);
    const bool vr = (j0 >= 0) && (j0 < 16);
    float Bt[5] = {B0, B1, B2, B3, B4};
    #pragma unroll
    for (int m = 0; m < 5; m++) {
        int  id = j0 - 4 + m;
        bool v  = vr && (id >= 0) && (id < 12);
        ix[m] = v ? id : 0;
        Bv[m] = v ? Bt[m] : 0.0f;
    }
}

__device__ __forceinline__ float silu_f(float x) {
    return x / (1.0f + __expf(-x));
}

__global__ __launch_bounds__(NTHR, 3)
void kan_fused_kernel(const float* __restrict__ node_rep,
                      const float* __restrict__ mlp_w,
                      const float* __restrict__ mlp_b,
                      const float* __restrict__ coef0,
                      const float* __restrict__ wb0,
                      const float* __restrict__ ws0,
                      const float* __restrict__ b0,
                      const float* __restrict__ coef1,
                      const float* __restrict__ wb1,
                      const float* __restrict__ ws1,
                      const float* __restrict__ b1,
                      float* __restrict__ out, int n)
{
    extern __shared__ __align__(16) char smem[];
    float* Abuf[2] = { (float*)smem, (float*)(smem + BUFBYTES) };
    float* Wbuf[2] = { (float*)(smem + ABYTES), (float*)(smem + BUFBYTES + ABYTES) };
    float (*Hs)[HID + 1] = (float (*)[HID + 1])smem;      // [256][33] alias (post-GEMM)
    float* csc0T = (float*)(smem + PRM_OFF);               // [12][193]: [b*193 + i*6 + o]
    float* wb0s  = csc0T + 2316;                           // [32*6]
    float* csc1T = wb0s + 192;                             // [12][7]
    float* wb1s  = csc1T + 84;
    float* b0s   = wb1s + 6;
    float* mlpbs = b0s + 6;
    float* b1s   = mlpbs + 32;

    const int tid  = threadIdx.x;
    const int w    = tid >> 5;
    const int l    = tid & 31;
    const int row0 = blockIdx.x * RPB;

    // ---- stage params ----
    for (int idx = tid; idx < NB * HID * W1; idx += NTHR) {
        int b = idx / (HID * W1), r = idx % (HID * W1);
        int i = r / W1, o = r % W1;
        csc0T[b * 193 + r] = coef0[i * (W1 * NB) + o * NB + b] * ws0[r];
    }
    for (int idx = tid; idx < HID * W1; idx += NTHR)
        wb0s[idx] = wb0[idx];
    if (tid < NB * 7) {
        int b = tid / 7, i = tid % 7;
        if (i < W1) csc1T[tid] = coef1[i * NB + b] * ws1[i];
    }
    if (tid < W1) { wb1s[tid] = wb1[tid]; b0s[tid] = b0[tid]; }
    if (tid < HID) mlpbs[tid] = mlp_b[tid];
    if (tid == 0) b1s[0] = b1[0];

    // ---- GEMM geometry: warp w -> rows [w*64, w*64+64) ----
    const int rg = (tid >> 2) & 7;
    const int cq = tid & 3;
    const int R0 = w * 64 + rg * 8;
    const int base0 = Pmap(R0);
    const int base1 = Pmap(R0 ^ 16);

    ull acc[8][4];
    #pragma unroll
    for (int r = 0; r < 8; r++)
        #pragma unroll
        for (int p = 0; p < 4; p++) acc[r][p] = 0ull;

    // ---- stager coordinates (proven conflict-free) ----
    const int sr = w * 8 + (l >> 2);
    const int k4 = l & 3;
    const int wk = tid >> 3;
    const int wc = tid & 7;
    const int s1 = ((k4 >> 1) & 1) << 4;
    const int kb = k4 * 4;
    int pp[8];
    #pragma unroll
    for (int j = 0; j < 8; j++) pp[j] = Pmap((sr + 32 * j) ^ s1);

    float4 pa[8];
    float4 pw;

    // prologue: prefetch tile 0, stage into buf0
    #pragma unroll
    for (int j = 0; j < 8; j++) {
        int gr = row0 + sr + 32 * j;
        pa[j] = make_float4(0.f, 0.f, 0.f, 0.f);
        if (gr < n)
            pa[j] = *(const float4*)&node_rep[(size_t)gr * D_IN + k4 * 4];
    }
    pw = *(const float4*)&mlp_w[(size_t)wk * HID + wc * 4];
    {
        float* As = Abuf[0];
        #pragma unroll
        for (int j = 0; j < 8; j++) {
            As[(kb + 0) * ASTR + pp[j]] = pa[j].x;
            As[(kb + 1) * ASTR + pp[j]] = pa[j].y;
            As[(kb + 2) * ASTR + pp[j]] = pa[j].z;
            As[(kb + 3) * ASTR + pp[j]] = pa[j].w;
        }
        *(float4*)&Wbuf[0][wk * WSTR + wc * 4] = pw;
    }
    __syncthreads();

    for (int t = 0; t < NTILES; t++) {
        const int cur = t & 1;
        const float* As = Abuf[cur];
        const float* Ws = Wbuf[cur];

        // ---- prefetch tile t+1 (LDG latency hides under compute) ----
        const bool more = (t + 1 < NTILES);
        if (more) {
            const int kc = (t + 1) * KC;
            #pragma unroll
            for (int j = 0; j < 8; j++) {
                int gr = row0 + sr + 32 * j;
                float4 v = make_float4(0.f, 0.f, 0.f, 0.f);
                if (gr < n)
                    v = *(const float4*)&node_rep[(size_t)gr * D_IN + kc + k4 * 4];
                pa[j] = v;
            }
            pw = *(const float4*)&mlp_w[(size_t)(kc + wk) * HID + wc * 4];
        }

        // ---- compute 16 k from buf[cur] ----
        #pragma unroll
        for (int k = 0; k < KC; k++) {
            const float* ab = &As[k * ASTR + (((k >> 3) & 1) ? base1 : base0)];
            float4 a0 = *(const float4*)ab;
            float4 a1 = *(const float4*)(ab + 4);
            ull ad0 = dup64(a0.x), ad1 = dup64(a0.y), ad2 = dup64(a0.z), ad3 = dup64(a0.w);
            ull ad4 = dup64(a1.x), ad5 = dup64(a1.y), ad6 = dup64(a1.z), ad7 = dup64(a1.w);
            const ull* wbp = (const ull*)&Ws[k * WSTR] + cq * 4;
            ulonglong2 wA = *(const ulonglong2*)(wbp);
            ulonglong2 wB = *(const ulonglong2*)(wbp + 2);
            acc[0][0] = ffma2(ad0, wA.x, acc[0][0]);
            acc[0][1] = ffma2(ad0, wA.y, acc[0][1]);
            acc[0][2] = ffma2(ad0, wB.x, acc[0][2]);
            acc[0][3] = ffma2(ad0, wB.y, acc[0][3]);
            acc[1][0] = ffma2(ad1, wA.x, acc[1][0]);
            acc[1][1] = ffma2(ad1, wA.y, acc[1][1]);
            acc[1][2] = ffma2(ad1, wB.x, acc[1][2]);
            acc[1][3] = ffma2(ad1, wB.y, acc[1][3]);
            acc[2][0] = ffma2(ad2, wA.x, acc[2][0]);
            acc[2][1] = ffma2(ad2, wA.y, acc[2][1]);
            acc[2][2] = ffma2(ad2, wB.x, acc[2][2]);
            acc[2][3] = ffma2(ad2, wB.y, acc[2][3]);
            acc[3][0] = ffma2(ad3, wA.x, acc[3][0]);
            acc[3][1] = ffma2(ad3, wA.y, acc[3][1]);
            acc[3][2] = ffma2(ad3, wB.x, acc[3][2]);
            acc[3][3] = ffma2(ad3, wB.y, acc[3][3]);
            acc[4][0] = ffma2(ad4, wA.x, acc[4][0]);
            acc[4][1] = ffma2(ad4, wA.y, acc[4][1]);
            acc[4][2] = ffma2(ad4, wB.x, acc[4][2]);
            acc[4][3] = ffma2(ad4, wB.y, acc[4][3]);
            acc[5][0] = ffma2(ad5, wA.x, acc[5][0]);
            acc[5][1] = ffma2(ad5, wA.y, acc[5][1]);
            acc[5][2] = ffma2(ad5, wB.x, acc[5][2]);
            acc[5][3] = ffma2(ad5, wB.y, acc[5][3]);
            acc[6][0] = ffma2(ad6, wA.x, acc[6][0]);
            acc[6][1] = ffma2(ad6, wA.y, acc[6][1]);
            acc[6][2] = ffma2(ad6, wB.x, acc[6][2]);
            acc[6][3] = ffma2(ad6, wB.y, acc[6][3]);
            acc[7][0] = ffma2(ad7, wA.x, acc[7][0]);
            acc[7][1] = ffma2(ad7, wA.y, acc[7][1]);
            acc[7][2] = ffma2(ad7, wB.x, acc[7][2]);
            acc[7][3] = ffma2(ad7, wB.y, acc[7][3]);
        }

        // ---- stage tile t+1 into the other buffer (safe: its readers
        //      finished before the barrier at the end of iteration t-1) ----
        if (more) {
            float* An = Abuf[cur ^ 1];
            #pragma unroll
            for (int j = 0; j < 8; j++) {
                An[(kb + 0) * ASTR + pp[j]] = pa[j].x;
                An[(kb + 1) * ASTR + pp[j]] = pa[j].y;
                An[(kb + 2) * ASTR + pp[j]] = pa[j].z;
                An[(kb + 3) * ASTR + pp[j]] = pa[j].w;
            }
            *(float4*)&Wbuf[cur ^ 1][wk * WSTR + wc * 4] = pw;
        }
        __syncthreads();
    }

    // ---- epilogue: acc -> Hs (+bias); tile buffers are dead ----
    #pragma unroll
    for (int r = 0; r < 8; r++) {
        #pragma unroll
        for (int p = 0; p < 4; p++) {
            const int col = cq * 8 + 2 * p;
            Hs[R0 + r][col    ] = __uint_as_float((unsigned)(acc[r][p]      )) + mlpbs[col];
            Hs[R0 + r][col + 1] = __uint_as_float((unsigned)(acc[r][p] >> 32)) + mlpbs[col + 1];
        }
    }
    __syncthreads();

    // ---- KAN: each thread owns 2 full rows end-to-end ----
    #pragma unroll 1
    for (int rr = tid; rr < RPB; rr += NTHR) {
        const int grow = row0 + rr;
        float acc6[W1] = {0.f, 0.f, 0.f, 0.f, 0.f, 0.f};
        #pragma unroll 1
        for (int i = 0; i < HID; i++) {
            float x = Hs[rr][i];
            float Bv[5]; int ix[5];
            basis5m(x, Bv, ix);
            float s = silu_f(x);
            const int base = i * W1;
            int a0 = ix[0] * 193 + base, a1 = ix[1] * 193 + base,
                a2 = ix[2] * 193 + base, a3 = ix[3] * 193 + base,
                a4 = ix[4] * 193 + base;
            #pragma unroll
            for (int o = 0; o < W1; o++) {
                float d =      Bv[0] * csc0T[a0 + o];
                d = fmaf(Bv[1], csc0T[a1 + o], d);
                d = fmaf(Bv[2], csc0T[a2 + o], d);
                d = fmaf(Bv[3], csc0T[a3 + o], d);
                d = fmaf(Bv[4], csc0T[a4 + o], d);
                acc6[o] = fmaf(s, wb0s[base + o], acc6[o] + d);
            }
        }
        float res = b1s[0];
        #pragma unroll 1
        for (int i = 0; i < W1; i++) {
            float x = acc6[i] + b0s[i];
            float Bv[5]; int ix[5];
            basis5m(x, Bv, ix);
            float d =      Bv[0] * csc1T[ix[0] * 7 + i];
            d = fmaf(Bv[1], csc1T[ix[1] * 7 + i], d);
            d = fmaf(Bv[2], csc1T[ix[2] * 7 + i], d);
            d = fmaf(Bv[3], csc1T[ix[3] * 7 + i], d);
            d = fmaf(Bv[4], csc1T[ix[4] * 7 + i], d);
            res += d + silu_f(x) * wb1s[i];
        }
        if (grow < n) out[grow] = res;
    }
}

extern "C" void kernel_launch(void* const* d_in, const int* in_sizes, int n_in,
                              void* d_out, int out_size) {
    const float* node_rep = (const float*)d_in[0];
    const float* mlp_w    = (const float*)d_in[1];
    const float* mlp_b    = (const float*)d_in[2];
    const float* coef0    = (const float*)d_in[3];
    const float* wb0      = (const float*)d_in[4];
    const float* ws0      = (const float*)d_in[5];
    const float* b0       = (const float*)d_in[6];
    const float* coef1    = (const float*)d_in[7];
    const float* wb1      = (const float*)d_in[8];
    const float* ws1      = (const float*)d_in[9];
    const float* b1       = (const float*)d_in[10];

    cudaFuncSetAttribute(kan_fused_kernel,
                         cudaFuncAttributeMaxDynamicSharedMemorySize, SMEM_SZ);

    int n = out_size;                       // 300000 rows, one output each
    int grid = (n + RPB - 1) / RPB;
    kan_fused_kernel<<<grid, NTHR, SMEM_SZ>>>(node_rep, mlp_w, mlp_b, coef0,
                                              wb0, ws0, b0, coef1, wb1, ws1,
                                              b1, (float*)d_out, n);
}

// round 13
// speedup vs baseline: 1.1539x; 1.1539x over previous
#include <cuda_runtime.h>

typedef unsigned long long ull;

#define D_IN   992
#define HID    32
#define W1     6
#define NB     12
#define KC     16               // k per tile
#define RPB    256              // rows per block
#define NTHR   128
#define NTILES 62               // 62*16 = 992
#define ASTR   388              // words per k-row of As (padded-block layout)
#define WSTR   36               // words per k-row of Ws

__device__ __forceinline__ ull ffma2(ull a, ull b, ull c) {
    ull d;
    asm("fma.rn.f32x2 %0, %1, %2, %3;" : "=l"(d) : "l"(a), "l"(b), "l"(c));
    return d;
}
__device__ __forceinline__ ull dup64(float a) {
    ull d;
    asm("mov.b64 %0, {%1, %1};" : "=l"(d) : "f"(a));
    return d;
}

// padded-block row map: 8-row groups + 4-word pad.
__device__ __forceinline__ int Pmap(int r) { return r + ((r >> 3) << 2); }

// Compact degree-4 uniform B-spline: 5 nonzero values + masked clamped indices.
__device__ __forceinline__ void basis5m(float x, float Bv[5], int ix[5]) {
    float u  = (x + 2.0f) * 4.0f;
    float fj = floorf(u);
    int   j0 = (int)fj;
    float s  = u - fj;
    float B0, B1, B2, B3, B4;
    B1 = s;  B0 = 1.0f - s;
    B2 = 0.5f * (s * B1);
    B1 = 0.5f * ((s + 1.0f) * B0 + (2.0f - s) * B1);
    B0 = 0.5f * ((1.0f - s) * B0);
    const float i3 = (1.0f / 3.0f);
    B3 = i3 * (s * B2);
    B2 = i3 * ((s + 1.0f) * B1 + (3.0f - s) * B2);
    B1 = i3 * ((s + 2.0f) * B0 + (2.0f - s) * B1);
    B0 = i3 * ((1.0f - s) * B0);
    B4 = 0.25f * (s * B3);
    B3 = 0.25f * ((s + 1.0f) * B2 + (4.0f - s) * B3);
    B2 = 0.25f * ((s + 2.0f) * B1 + (3.0f - s) * B2);
    B1 = 0.25f * ((s + 3.0f) * B0 + (2.0f - s) * B1);
    B0 = 0.25f * ((1.0f - s) * B0);
    const bool vr = (j0 >= 0) && (j0 < 16);
    float Bt[5] = {B0, B1, B2, B3, B4};
    #pragma unroll
    for (int m = 0; m < 5; m++) {
        int  id = j0 - 4 + m;
        bool v  = vr && (id >= 0) && (id < 12);
        ix[m] = v ? id : 0;
        Bv[m] = v ? Bt[m] : 0.0f;
    }
}

__device__ __forceinline__ float silu_f(float x) {
    return x / (1.0f + __expf(-x));
}

// smem byte offsets
#define WS_OFF   24832           // after As (16*388*4)
#define GEMM_REG 33792           // params start after the Hs alias region
#define SMEM_SZ  44352

__global__ __launch_bounds__(NTHR, 3)
void kan_fused_kernel(const float* __restrict__ node_rep,
                      const float* __restrict__ mlp_w,
                      const float* __restrict__ mlp_b,
                      const float* __restrict__ coef0,
                      const float* __restrict__ wb0,
                      const float* __restrict__ ws0,
                      const float* __restrict__ b0,
                      const float* __restrict__ coef1,
                      const float* __restrict__ wb1,
                      const float* __restrict__ ws1,
                      const float* __restrict__ b1,
                      float* __restrict__ out, int n)
{
    __shared__ __align__(16) char smem[SMEM_SZ];
    float* As = (float*)smem;                        // [16][388] (transposed, padded-block)
    float* Ws = (float*)(smem + WS_OFF);             // [16][36]  (row-major W tile)
    float (*Hs)[HID + 1] = (float (*)[HID + 1])smem; // [256][33] alias (post-GEMM)
    float* csc0T = (float*)(smem + GEMM_REG);        // [12][193]: [b*193 + i*6 + o]
    float* wb0s  = csc0T + 2316;                     // [32*6]
    float* csc1T = wb0s + 192;                       // [12][7]:  [b*7 + i]
    float* wb1s  = csc1T + 84;                       // [6]
    float* b0s   = wb1s + 6;                         // [6]
    float* mlpbs = b0s + 6;                          // [32]
    float* b1s   = mlpbs + 32;                       // [1]

    const int tid  = threadIdx.x;
    const int w    = tid >> 5;
    const int l    = tid & 31;
    const int row0 = blockIdx.x * RPB;
    // stagger: co-resident CTAs (consecutive blockIdx) start on different
    // tiles so their barrier/staging windows interleave instead of colliding.
    const int toff = blockIdx.x % NTILES;

    // ---- stage params ----
    for (int idx = tid; idx < NB * HID * W1; idx += NTHR) {
        int b = idx / (HID * W1), r = idx % (HID * W1);
        int i = r / W1, o = r % W1;
        csc0T[b * 193 + r] = coef0[i * (W1 * NB) + o * NB + b] * ws0[r];
    }
    for (int idx = tid; idx < HID * W1; idx += NTHR)
        wb0s[idx] = wb0[idx];
    if (tid < NB * 7) {
        int b = tid / 7, i = tid % 7;
        if (i < W1) csc1T[tid] = coef1[i * NB + b] * ws1[i];
    }
    if (tid < W1) { wb1s[tid] = wb1[tid]; b0s[tid] = b0[tid]; }
    if (tid < HID) mlpbs[tid] = mlp_b[tid];
    if (tid == 0) b1s[0] = b1[0];

    // ---- GEMM geometry: warp w -> rows [w*64, w*64+64) ----
    const int rg = (tid >> 2) & 7;
    const int cq = tid & 3;
    const int R0 = w * 64 + rg * 8;
    const int base0 = Pmap(R0);
    const int base1 = Pmap(R0 ^ 16);

    ull acc[8][4];
    #pragma unroll
    for (int r = 0; r < 8; r++)
        #pragma unroll
        for (int p = 0; p < 4; p++) acc[r][p] = 0ull;

    // ---- stager coordinates (proven conflict-free) ----
    const int sr = w * 8 + (l >> 2);
    const int k4 = l & 3;
    const int wk = tid >> 3;
    const int wc = tid & 7;
    const int s1 = ((k4 >> 1) & 1) << 4;
    const int kb = k4 * 4;
    int pp[8];
    #pragma unroll
    for (int j = 0; j < 8; j++) pp[j] = Pmap((sr + 32 * j) ^ s1);

    float4 pa[8];
    float4 pw;

    // prologue: prefetch tile toff
    {
        const int kc = toff * KC;
        #pragma unroll
        for (int j = 0; j < 8; j++) {
            int gr = row0 + sr + 32 * j;
            pa[j] = make_float4(0.f, 0.f, 0.f, 0.f);
            if (gr < n)
                pa[j] = *(const float4*)&node_rep[(size_t)gr * D_IN + kc + k4 * 4];
        }
        pw = *(const float4*)&mlp_w[(size_t)(kc + wk) * HID + wc * 4];
    }

    int t = toff;
    for (int tt = 0; tt < NTILES; tt++) {
        __syncthreads();                 // previous tile's compute done
        // ---- STS current tile ----
        #pragma unroll
        for (int j = 0; j < 8; j++) {
            As[(kb + 0) * ASTR + pp[j]] = pa[j].x;
            As[(kb + 1) * ASTR + pp[j]] = pa[j].y;
            As[(kb + 2) * ASTR + pp[j]] = pa[j].z;
            As[(kb + 3) * ASTR + pp[j]] = pa[j].w;
        }
        *(float4*)&Ws[wk * WSTR + wc * 4] = pw;
        __syncthreads();

        // ---- prefetch next tile in the staggered sequence ----
        if (tt + 1 < NTILES) {
            int tn = t + 1; if (tn >= NTILES) tn = 0;
            const int kc = tn * KC;
            #pragma unroll
            for (int j = 0; j < 8; j++) {
                int gr = row0 + sr + 32 * j;
                float4 v = make_float4(0.f, 0.f, 0.f, 0.f);
                if (gr < n)
                    v = *(const float4*)&node_rep[(size_t)gr * D_IN + kc + k4 * 4];
                pa[j] = v;
            }
            pw = *(const float4*)&mlp_w[(size_t)(kc + wk) * HID + wc * 4];
        }

        // ---- compute 16 k: per k 4 conflict-free LDS.128 + 8 dups + 32 FFMA2 ----
        #pragma unroll
        for (int k = 0; k < KC; k++) {
            const float* ab = &As[k * ASTR + (((k >> 3) & 1) ? base1 : base0)];
            float4 a0 = *(const float4*)ab;
            float4 a1 = *(const float4*)(ab + 4);
            ull ad0 = dup64(a0.x), ad1 = dup64(a0.y), ad2 = dup64(a0.z), ad3 = dup64(a0.w);
            ull ad4 = dup64(a1.x), ad5 = dup64(a1.y), ad6 = dup64(a1.z), ad7 = dup64(a1.w);
            const ull* wbp = (const ull*)&Ws[k * WSTR] + cq * 4;
            ulonglong2 wA = *(const ulonglong2*)(wbp);
            ulonglong2 wB = *(const ulonglong2*)(wbp + 2);
            acc[0][0] = ffma2(ad0, wA.x, acc[0][0]);
            acc[0][1] = ffma2(ad0, wA.y, acc[0][1]);
            acc[0][2] = ffma2(ad0, wB.x, acc[0][2]);
            acc[0][3] = ffma2(ad0, wB.y, acc[0][3]);
            acc[1][0] = ffma2(ad1, wA.x, acc[1][0]);
            acc[1][1] = ffma2(ad1, wA.y, acc[1][1]);
            acc[1][2] = ffma2(ad1, wB.x, acc[1][2]);
            acc[1][3] = ffma2(ad1, wB.y, acc[1][3]);
            acc[2][0] = ffma2(ad2, wA.x, acc[2][0]);
            acc[2][1] = ffma2(ad2, wA.y, acc[2][1]);
            acc[2][2] = ffma2(ad2, wB.x, acc[2][2]);
            acc[2][3] = ffma2(ad2, wB.y, acc[2][3]);
            acc[3][0] = ffma2(ad3, wA.x, acc[3][0]);
            acc[3][1] = ffma2(ad3, wA.y, acc[3][1]);
            acc[3][2] = ffma2(ad3, wB.x, acc[3][2]);
            acc[3][3] = ffma2(ad3, wB.y, acc[3][3]);
            acc[4][0] = ffma2(ad4, wA.x, acc[4][0]);
            acc[4][1] = ffma2(ad4, wA.y, acc[4][1]);
            acc[4][2] = ffma2(ad4, wB.x, acc[4][2]);
            acc[4][3] = ffma2(ad4, wB.y, acc[4][3]);
            acc[5][0] = ffma2(ad5, wA.x, acc[5][0]);
            acc[5][1] = ffma2(ad5, wA.y, acc[5][1]);
            acc[5][2] = ffma2(ad5, wB.x, acc[5][2]);
            acc[5][3] = ffma2(ad5, wB.y, acc[5][3]);
            acc[6][0] = ffma2(ad6, wA.x, acc[6][0]);
            acc[6][1] = ffma2(ad6, wA.y, acc[6][1]);
            acc[6][2] = ffma2(ad6, wB.x, acc[6][2]);
            acc[6][3] = ffma2(ad6, wB.y, acc[6][3]);
            acc[7][0] = ffma2(ad7, wA.x, acc[7][0]);
            acc[7][1] = ffma2(ad7, wA.y, acc[7][1]);
            acc[7][2] = ffma2(ad7, wB.x, acc[7][2]);
            acc[7][3] = ffma2(ad7, wB.y, acc[7][3]);
        }

        t++; if (t >= NTILES) t = 0;
    }
    __syncthreads();   // GEMM SMEM dead; safe to overwrite with Hs

    // ---- epilogue: acc -> Hs (+bias) ----
    #pragma unroll
    for (int r = 0; r < 8; r++) {
        #pragma unroll
        for (int p = 0; p < 4; p++) {
            const int col = cq * 8 + 2 * p;
            Hs[R0 + r][col    ] = __uint_as_float((unsigned)(acc[r][p]      )) + mlpbs[col];
            Hs[R0 + r][col + 1] = __uint_as_float((unsigned)(acc[r][p] >> 32)) + mlpbs[col + 1];
        }
    }
    __syncthreads();

    // ---- KAN: each thread owns 2 full rows end-to-end ----
    #pragma unroll 1
    for (int rr = tid; rr < RPB; rr += NTHR) {
        const int grow = row0 + rr;
        float acc6[W1] = {0.f, 0.f, 0.f, 0.f, 0.f, 0.f};
        #pragma unroll 1
        for (int i = 0; i < HID; i++) {
            float x = Hs[rr][i];
            float Bv[5]; int ix[5];
            basis5m(x, Bv, ix);
            float s = silu_f(x);
            const int base = i * W1;
            int a0 = ix[0] * 193 + base, a1 = ix[1] * 193 + base,
                a2 = ix[2] * 193 + base, a3 = ix[3] * 193 + base,
                a4 = ix[4] * 193 + base;
            #pragma unroll
            for (int o = 0; o < W1; o++) {
                float d =      Bv[0] * csc0T[a0 + o];
                d = fmaf(Bv[1], csc0T[a1 + o], d);
                d = fmaf(Bv[2], csc0T[a2 + o], d);
                d = fmaf(Bv[3], csc0T[a3 + o], d);
                d = fmaf(Bv[4], csc0T[a4 + o], d);
                acc6[o] = fmaf(s, wb0s[base + o], acc6[o] + d);
            }
        }
        float res = b1s[0];
        #pragma unroll 1
        for (int i = 0; i < W1; i++) {
            float x = acc6[i] + b0s[i];
            float Bv[5]; int ix[5];
            basis5m(x, Bv, ix);
            float d =      Bv[0] * csc1T[ix[0] * 7 + i];
            d = fmaf(Bv[1], csc1T[ix[1] * 7 + i], d);
            d = fmaf(Bv[2], csc1T[ix[2] * 7 + i], d);
            d = fmaf(Bv[3], csc1T[ix[3] * 7 + i], d);
            d = fmaf(Bv[4], csc1T[ix[4] * 7 + i], d);
            res += d + silu_f(x) * wb1s[i];
        }
        if (grow < n) out[grow] = res;
    }
}

extern "C" void kernel_launch(void* const* d_in, const int* in_sizes, int n_in,
                              void* d_out, int out_size) {
    const float* node_rep = (const float*)d_in[0];
    const float* mlp_w    = (const float*)d_in[1];
    const float* mlp_b    = (const float*)d_in[2];
    const float* coef0    = (const float*)d_in[3];
    const float* wb0      = (const float*)d_in[4];
    const float* ws0      = (const float*)d_in[5];
    const float* b0       = (const float*)d_in[6];
    const float* coef1    = (const float*)d_in[7];
    const float* wb1      = (const float*)d_in[8];
    const float* ws1      = (const float*)d_in[9];
    const float* b1       = (const float*)d_in[10];

    int n = out_size;                       // 300000 rows, one output each
    int grid = (n + RPB - 1) / RPB;
    kan_fused_kernel<<<grid, NTHR>>>(node_rep, mlp_w, mlp_b, coef0, wb0, ws0,
                                     b0, coef1, wb1, ws1, b1,
                                     (float*)d_out, n);
}

// round 14
// speedup vs baseline: 1.5550x; 1.3476x over previous
#include <cuda_runtime.h>
#include <cuda_bf16.h>
#include <cstdint>

#define D_IN   992
#define HID    32
#define W1     6
#define NB     12
#define KC     32               // k per tile
#define RPB    128              // rows per block
#define NTHR   128
#define NTILES 31               // 31*32 = 992 exactly
#define APITCH 80               // bytes per bf16 row (32*2 + 16 pad): bank-partition pitch

// smem byte offsets
#define AHI_OFF 0
#define ALO_OFF 10240
#define BHI_OFF 20480
#define BLO_OFF 23040
#define PRM_OFF 25600
#define SMEM_SZ 36160

__device__ __forceinline__ uint32_t smem_u32(const void* p) {
    uint32_t a;
    asm("{ .reg .u64 t; cvta.to.shared.u64 t, %1; cvt.u32.u64 %0, t; }" : "=r"(a) : "l"(p));
    return a;
}

#define LDSM4(r0, r1, r2, r3, addr) \
    asm volatile("ldmatrix.sync.aligned.m8n8.x4.shared.b16 {%0,%1,%2,%3}, [%4];" \
                 : "=r"(r0), "=r"(r1), "=r"(r2), "=r"(r3) : "r"(addr))
#define LDSM4T(r0, r1, r2, r3, addr) \
    asm volatile("ldmatrix.sync.aligned.m8n8.x4.trans.shared.b16 {%0,%1,%2,%3}, [%4];" \
                 : "=r"(r0), "=r"(r1), "=r"(r2), "=r"(r3) : "r"(addr))
#define MMA16816(d, a, b0v, b1v) \
    asm volatile("mma.sync.aligned.m16n8k16.row.col.f32.bf16.bf16.f32 " \
                 "{%0,%1,%2,%3}, {%4,%5,%6,%7}, {%8,%9}, {%0,%1,%2,%3};" \
                 : "+f"((d)[0]), "+f"((d)[1]), "+f"((d)[2]), "+f"((d)[3]) \
                 : "r"((a)[0]), "r"((a)[1]), "r"((a)[2]), "r"((a)[3]), \
                   "r"(b0v), "r"(b1v))

__device__ __forceinline__ uint32_t pack_bf16x2(float lo_el, float hi_el) {
    __nv_bfloat162 h = __floats2bfloat162_rn(lo_el, hi_el);   // .x (low) = first arg
    return *reinterpret_cast<uint32_t*>(&h);
}

// split one float4 into hi-pair regs and lo-pair regs (bf16x2 each)
__device__ __forceinline__ void split4(float4 v, uint32_t& h01, uint32_t& h23,
                                       uint32_t& l01, uint32_t& l23) {
    __nv_bfloat16 b0 = __float2bfloat16(v.x);
    __nv_bfloat16 b1 = __float2bfloat16(v.y);
    __nv_bfloat16 b2 = __float2bfloat16(v.z);
    __nv_bfloat16 b3 = __float2bfloat16(v.w);
    __nv_bfloat162 p01; p01.x = b0; p01.y = b1;
    __nv_bfloat162 p23; p23.x = b2; p23.y = b3;
    h01 = *reinterpret_cast<uint32_t*>(&p01);
    h23 = *reinterpret_cast<uint32_t*>(&p23);
    l01 = pack_bf16x2(v.x - __bfloat162float(b0), v.y - __bfloat162float(b1));
    l23 = pack_bf16x2(v.z - __bfloat162float(b2), v.w - __bfloat162float(b3));
}

// Compact degree-4 uniform B-spline: 5 nonzero values + masked clamped indices.
__device__ __forceinline__ void basis5m(float x, float Bv[5], int ix[5]) {
    float u  = (x + 2.0f) * 4.0f;
    float fj = floorf(u);
    int   j0 = (int)fj;
    float s  = u - fj;
    float B0, B1, B2, B3, B4;
    B1 = s;  B0 = 1.0f - s;
    B2 = 0.5f * (s * B1);
    B1 = 0.5f * ((s + 1.0f) * B0 + (2.0f - s) * B1);
    B0 = 0.5f * ((1.0f - s) * B0);
    const float i3 = (1.0f / 3.0f);
    B3 = i3 * (s * B2);
    B2 = i3 * ((s + 1.0f) * B1 + (3.0f - s) * B2);
    B1 = i3 * ((s + 2.0f) * B0 + (2.0f - s) * B1);
    B0 = i3 * ((1.0f - s) * B0);
    B4 = 0.25f * (s * B3);
    B3 = 0.25f * ((s + 1.0f) * B2 + (4.0f - s) * B3);
    B2 = 0.25f * ((s + 2.0f) * B1 + (3.0f - s) * B2);
    B1 = 0.25f * ((s + 3.0f) * B0 + (2.0f - s) * B1);
    B0 = 0.25f * ((1.0f - s) * B0);
    const bool vr = (j0 >= 0) && (j0 < 16);
    float Bt[5] = {B0, B1, B2, B3, B4};
    #pragma unroll
    for (int m = 0; m < 5; m++) {
        int  id = j0 - 4 + m;
        bool v  = vr && (id >= 0) && (id < 12);
        ix[m] = v ? id : 0;
        Bv[m] = v ? Bt[m] : 0.0f;
    }
}

__device__ __forceinline__ float silu_f(float x) {
    return x / (1.0f + __expf(-x));
}

__global__ __launch_bounds__(NTHR, 3)
void kan_mma_kernel(const float* __restrict__ node_rep,
                    const float* __restrict__ mlp_w,
                    const float* __restrict__ mlp_b,
                    const float* __restrict__ coef0,
                    const float* __restrict__ wb0,
                    const float* __restrict__ ws0,
                    const float* __restrict__ b0,
                    const float* __restrict__ coef1,
                    const float* __restrict__ wb1,
                    const float* __restrict__ ws1,
                    const float* __restrict__ b1,
                    float* __restrict__ out, int n)
{
    __shared__ __align__(16) char smem[SMEM_SZ];
    const uint32_t sb = smem_u32(smem);
    float (*Hs)[HID + 1] = (float (*)[HID + 1])smem;    // [128][33] alias (post-GEMM)
    float* csc0T = (float*)(smem + PRM_OFF);            // [12][193]
    float* wb0s  = csc0T + 2316;
    float* csc1T = wb0s + 192;                          // [12][7]
    float* wb1s  = csc1T + 84;
    float* b0s   = wb1s + 6;
    float* mlpbs = b0s + 6;
    float* b1s   = mlpbs + 32;

    const int tid  = threadIdx.x;
    const int w    = tid >> 5;
    const int l    = tid & 31;
    const int row0 = blockIdx.x * RPB;
    const int toff = blockIdx.x % NTILES;     // tile-order stagger (R13 win)

    // ---- stage params ----
    for (int idx = tid; idx < NB * HID * W1; idx += NTHR) {
        int b = idx / (HID * W1), r = idx % (HID * W1);
        int i = r / W1, o = r % W1;
        csc0T[b * 193 + r] = coef0[i * (W1 * NB) + o * NB + b] * ws0[r];
    }
    for (int idx = tid; idx < HID * W1; idx += NTHR)
        wb0s[idx] = wb0[idx];
    if (tid < NB * 7) {
        int b = tid / 7, i = tid % 7;
        if (i < W1) csc1T[tid] = coef1[i * NB + b] * ws1[i];
    }
    if (tid < W1) { wb1s[tid] = wb1[tid]; b0s[tid] = b0[tid]; }
    if (tid < HID) mlpbs[tid] = mlp_b[tid];
    if (tid == 0) b1s[0] = b1[0];

    // ---- MMA geometry: warp w -> rows [w*32, w*32+32), all 32 cols ----
    float acc[2][4][4];
    #pragma unroll
    for (int mt = 0; mt < 2; mt++)
        #pragma unroll
        for (int nt = 0; nt < 4; nt++)
            #pragma unroll
            for (int q = 0; q < 4; q++) acc[mt][nt][q] = 0.0f;

    // ldmatrix lane coordinates
    const int g8 = l >> 3;           // sub-matrix id 0..3
    const int r8 = l & 7;
    const uint32_t acolb = (uint32_t)((g8 >> 1) << 4);              // 0 or 16 bytes
    const uint32_t arowb = (uint32_t)((w << 5) + ((g8 & 1) << 3) + r8) * APITCH;
    const uint32_t bkrow = (uint32_t)(((g8 & 1) << 3) + r8) * APITCH;
    const uint32_t aA = sb + AHI_OFF + arowb + acolb;   // + mt*1280 + kk*32 (+10240 for lo)
    const uint32_t bB = sb + BHI_OFF + bkrow + acolb;   // + nh*32 + kk*1280 (+2560 for lo)

    // staging coordinates
    const int ar = tid >> 3;         // A base row (0..15), rows ar + 16j
    const int ac = tid & 7;          // float4 col (0..7)
    const int wr = tid >> 2;         // W k-row (0..31)
    const int wq = tid & 3;          // W col-quarter

    float4 pa[8];
    float4 pw0, pw1;

    // prologue: prefetch tile toff
    {
        const int kc = toff * KC;
        #pragma unroll
        for (int j = 0; j < 8; j++) {
            int gr = row0 + ar + 16 * j;
            pa[j] = make_float4(0.f, 0.f, 0.f, 0.f);
            if (gr < n)
                pa[j] = *(const float4*)&node_rep[(size_t)gr * D_IN + kc + ac * 4];
        }
        pw0 = *(const float4*)&mlp_w[(size_t)(kc + wr) * HID + wq * 8];
        pw1 = *(const float4*)&mlp_w[(size_t)(kc + wr) * HID + wq * 8 + 4];
    }

    int t = toff;
    for (int tt = 0; tt < NTILES; tt++) {
        __syncthreads();
        // ---- STS: split fp32 -> bf16 hi/lo, store tiles ----
        #pragma unroll
        for (int j = 0; j < 8; j++) {
            const int R = ar + 16 * j;
            uint32_t h01, h23, l01, l23;
            split4(pa[j], h01, h23, l01, l23);
            char* hp = smem + AHI_OFF + R * APITCH + ac * 8;
            char* lp = smem + ALO_OFF + R * APITCH + ac * 8;
            *(uint2*)hp = make_uint2(h01, h23);
            *(uint2*)lp = make_uint2(l01, l23);
        }
        {
            uint32_t h01, h23, l01, l23, h45, h67, l45, l67;
            split4(pw0, h01, h23, l01, l23);
            split4(pw1, h45, h67, l45, l67);
            char* hp = smem + BHI_OFF + wr * APITCH + wq * 16;
            char* lp = smem + BLO_OFF + wr * APITCH + wq * 16;
            *(uint4*)hp = make_uint4(h01, h23, h45, h67);
            *(uint4*)lp = make_uint4(l01, l23, l45, l67);
        }
        __syncthreads();

        // ---- prefetch next tile in staggered order ----
        if (tt + 1 < NTILES) {
            int tn = t + 1; if (tn >= NTILES) tn = 0;
            const int kc = tn * KC;
            #pragma unroll
            for (int j = 0; j < 8; j++) {
                int gr = row0 + ar + 16 * j;
                float4 v = make_float4(0.f, 0.f, 0.f, 0.f);
                if (gr < n)
                    v = *(const float4*)&node_rep[(size_t)gr * D_IN + kc + ac * 4];
                pa[j] = v;
            }
            pw0 = *(const float4*)&mlp_w[(size_t)(kc + wr) * HID + wq * 8];
            pw1 = *(const float4*)&mlp_w[(size_t)(kc + wr) * HID + wq * 8 + 4];
        }

        // ---- compute: 2 k16 halves x (8 ldmatrix + 24 mma) ----
        #pragma unroll
        for (int kk = 0; kk < 2; kk++) {
            uint32_t ah[2][4], al[2][4], bh[8], bl[8];
            const uint32_t ka = aA + kk * 32;
            const uint32_t kb = bB + kk * (16 * APITCH);
            LDSM4(ah[0][0], ah[0][1], ah[0][2], ah[0][3], ka);
            LDSM4(ah[1][0], ah[1][1], ah[1][2], ah[1][3], ka + 16 * APITCH);
            LDSM4(al[0][0], al[0][1], al[0][2], al[0][3], ka + 10240);
            LDSM4(al[1][0], al[1][1], al[1][2], al[1][3], ka + 10240 + 16 * APITCH);
            LDSM4T(bh[0], bh[1], bh[2], bh[3], kb);
            LDSM4T(bh[4], bh[5], bh[6], bh[7], kb + 32);
            LDSM4T(bl[0], bl[1], bl[2], bl[3], kb + 2560);
            LDSM4T(bl[4], bl[5], bl[6], bl[7], kb + 2560 + 32);
            #pragma unroll
            for (int mt = 0; mt < 2; mt++)
                #pragma unroll
                for (int nt = 0; nt < 4; nt++) {
                    MMA16816(acc[mt][nt], ah[mt], bh[2 * nt], bh[2 * nt + 1]);
                    MMA16816(acc[mt][nt], ah[mt], bl[2 * nt], bl[2 * nt + 1]);
                    MMA16816(acc[mt][nt], al[mt], bh[2 * nt], bh[2 * nt + 1]);
                }
        }

        t++; if (t >= NTILES) t = 0;
    }
    __syncthreads();   // GEMM SMEM dead; overwrite with Hs

    // ---- epilogue: fragments -> Hs (+bias) ----
    {
        const int g = l >> 2, tq = l & 3;
        #pragma unroll
        for (int mt = 0; mt < 2; mt++) {
            const int R = w * 32 + mt * 16 + g;
            #pragma unroll
            for (int nt = 0; nt < 4; nt++) {
                const int C = nt * 8 + tq * 2;
                Hs[R    ][C    ] = acc[mt][nt][0] + mlpbs[C];
                Hs[R    ][C + 1] = acc[mt][nt][1] + mlpbs[C + 1];
                Hs[R + 8][C    ] = acc[mt][nt][2] + mlpbs[C];
                Hs[R + 8][C + 1] = acc[mt][nt][3] + mlpbs[C + 1];
            }
        }
    }
    __syncthreads();

    // ---- KAN: one thread per row ----
    {
        const int rr = tid;
        const int grow = row0 + rr;
        float acc6[W1] = {0.f, 0.f, 0.f, 0.f, 0.f, 0.f};
        #pragma unroll 1
        for (int i = 0; i < HID; i++) {
            float x = Hs[rr][i];
            float Bv[5]; int ix[5];
            basis5m(x, Bv, ix);
            float s = silu_f(x);
            const int base = i * W1;
            int a0 = ix[0] * 193 + base, a1 = ix[1] * 193 + base,
                a2 = ix[2] * 193 + base, a3 = ix[3] * 193 + base,
                a4 = ix[4] * 193 + base;
            #pragma unroll
            for (int o = 0; o < W1; o++) {
                float d =      Bv[0] * csc0T[a0 + o];
                d = fmaf(Bv[1], csc0T[a1 + o], d);
                d = fmaf(Bv[2], csc0T[a2 + o], d);
                d = fmaf(Bv[3], csc0T[a3 + o], d);
                d = fmaf(Bv[4], csc0T[a4 + o], d);
                acc6[o] = fmaf(s, wb0s[base + o], acc6[o] + d);
            }
        }
        float res = b1s[0];
        #pragma unroll 1
        for (int i = 0; i < W1; i++) {
            float x = acc6[i] + b0s[i];
            float Bv[5]; int ix[5];
            basis5m(x, Bv, ix);
            float d =      Bv[0] * csc1T[ix[0] * 7 + i];
            d = fmaf(Bv[1], csc1T[ix[1] * 7 + i], d);
            d = fmaf(Bv[2], csc1T[ix[2] * 7 + i], d);
            d = fmaf(Bv[3], csc1T[ix[3] * 7 + i], d);
            d = fmaf(Bv[4], csc1T[ix[4] * 7 + i], d);
            res += d + silu_f(x) * wb1s[i];
        }
        if (grow < n) out[grow] = res;
    }
}

extern "C" void kernel_launch(void* const* d_in, const int* in_sizes, int n_in,
                              void* d_out, int out_size) {
    const float* node_rep = (const float*)d_in[0];
    const float* mlp_w    = (const float*)d_in[1];
    const float* mlp_b    = (const float*)d_in[2];
    const float* coef0    = (const float*)d_in[3];
    const float* wb0      = (const float*)d_in[4];
    const float* ws0      = (const float*)d_in[5];
    const float* b0       = (const float*)d_in[6];
    const float* coef1    = (const float*)d_in[7];
    const float* wb1      = (const float*)d_in[8];
    const float* ws1      = (const float*)d_in[9];
    const float* b1       = (const float*)d_in[10];

    int n = out_size;                       // 300000 rows, one output each
    int grid = (n + RPB - 1) / RPB;
    kan_mma_kernel<<<grid, NTHR>>>(node_rep, mlp_w, mlp_b, coef0, wb0, ws0,
                                   b0, coef1, wb1, ws1, b1,
                                   (float*)d_out, n);
}

// round 15
// speedup vs baseline: 1.6160x; 1.0392x over previous
#include <cuda_runtime.h>
#include <cuda_bf16.h>
#include <cstdint>

#define D_IN   992
#define HID    32
#define W1     6
#define NB     12
#define KC     16               // k per tile
#define RPB    128              // rows per block
#define NTHR   128
#define NTILES 62               // 62*16 = 992
#define APA    48               // A row pitch bytes (16 bf16 = 32B + 16 pad)
#define APB    80               // B row pitch bytes (32 bf16 = 64B + 16 pad)

// smem byte offsets
#define AHI_OFF 0               // 128*48 = 6144
#define ALO_OFF 6144
#define BHI_OFF 12288           // 16*80 = 1280
#define BLO_OFF 13568
#define PRM_OFF 16896           // Hs alias needs 128*33*4 = 16896
#define SMEM_SZ 27456

__device__ __forceinline__ uint32_t smem_u32(const void* p) {
    uint32_t a;
    asm("{ .reg .u64 t; cvta.to.shared.u64 t, %1; cvt.u32.u64 %0, t; }" : "=r"(a) : "l"(p));
    return a;
}

#define LDSM4(r0, r1, r2, r3, addr) \
    asm volatile("ldmatrix.sync.aligned.m8n8.x4.shared.b16 {%0,%1,%2,%3}, [%4];" \
                 : "=r"(r0), "=r"(r1), "=r"(r2), "=r"(r3) : "r"(addr))
#define LDSM4T(r0, r1, r2, r3, addr) \
    asm volatile("ldmatrix.sync.aligned.m8n8.x4.trans.shared.b16 {%0,%1,%2,%3}, [%4];" \
                 : "=r"(r0), "=r"(r1), "=r"(r2), "=r"(r3) : "r"(addr))
#define MMA16816(d, a, b0v, b1v) \
    asm volatile("mma.sync.aligned.m16n8k16.row.col.f32.bf16.bf16.f32 " \
                 "{%0,%1,%2,%3}, {%4,%5,%6,%7}, {%8,%9}, {%0,%1,%2,%3};" \
                 : "+f"((d)[0]), "+f"((d)[1]), "+f"((d)[2]), "+f"((d)[3]) \
                 : "r"((a)[0]), "r"((a)[1]), "r"((a)[2]), "r"((a)[3]), \
                   "r"(b0v), "r"(b1v))

__device__ __forceinline__ uint32_t pack_bf16x2(float lo_el, float hi_el) {
    __nv_bfloat162 h = __floats2bfloat162_rn(lo_el, hi_el);
    return *reinterpret_cast<uint32_t*>(&h);
}

__device__ __forceinline__ void split4(float4 v, uint32_t& h01, uint32_t& h23,
                                       uint32_t& l01, uint32_t& l23) {
    __nv_bfloat16 b0 = __float2bfloat16(v.x);
    __nv_bfloat16 b1 = __float2bfloat16(v.y);
    __nv_bfloat16 b2 = __float2bfloat16(v.z);
    __nv_bfloat16 b3 = __float2bfloat16(v.w);
    __nv_bfloat162 p01; p01.x = b0; p01.y = b1;
    __nv_bfloat162 p23; p23.x = b2; p23.y = b3;
    h01 = *reinterpret_cast<uint32_t*>(&p01);
    h23 = *reinterpret_cast<uint32_t*>(&p23);
    l01 = pack_bf16x2(v.x - __bfloat162float(b0), v.y - __bfloat162float(b1));
    l23 = pack_bf16x2(v.z - __bfloat162float(b2), v.w - __bfloat162float(b3));
}

// Compact degree-4 uniform B-spline: 5 nonzero values + masked clamped indices.
__device__ __forceinline__ void basis5m(float x, float Bv[5], int ix[5]) {
    float u  = (x + 2.0f) * 4.0f;
    float fj = floorf(u);
    int   j0 = (int)fj;
    float s  = u - fj;
    float B0, B1, B2, B3, B4;
    B1 = s;  B0 = 1.0f - s;
    B2 = 0.5f * (s * B1);
    B1 = 0.5f * ((s + 1.0f) * B0 + (2.0f - s) * B1);
    B0 = 0.5f * ((1.0f - s) * B0);
    const float i3 = (1.0f / 3.0f);
    B3 = i3 * (s * B2);
    B2 = i3 * ((s + 1.0f) * B1 + (3.0f - s) * B2);
    B1 = i3 * ((s + 2.0f) * B0 + (2.0f - s) * B1);
    B0 = i3 * ((1.0f - s) * B0);
    B4 = 0.25f * (s * B3);
    B3 = 0.25f * ((s + 1.0f) * B2 + (4.0f - s) * B3);
    B2 = 0.25f * ((s + 2.0f) * B1 + (3.0f - s) * B2);
    B1 = 0.25f * ((s + 3.0f) * B0 + (2.0f - s) * B1);
    B0 = 0.25f * ((1.0f - s) * B0);
    const bool vr = (j0 >= 0) && (j0 < 16);
    float Bt[5] = {B0, B1, B2, B3, B4};
    #pragma unroll
    for (int m = 0; m < 5; m++) {
        int  id = j0 - 4 + m;
        bool v  = vr && (id >= 0) && (id < 12);
        ix[m] = v ? id : 0;
        Bv[m] = v ? Bt[m] : 0.0f;
    }
}

__device__ __forceinline__ float silu_f(float x) {
    return x / (1.0f + __expf(-x));
}

__global__ __launch_bounds__(NTHR, 4)
void kan_mma_kernel(const float* __restrict__ node_rep,
                    const float* __restrict__ mlp_w,
                    const float* __restrict__ mlp_b,
                    const float* __restrict__ coef0,
                    const float* __restrict__ wb0,
                    const float* __restrict__ ws0,
                    const float* __restrict__ b0,
                    const float* __restrict__ coef1,
                    const float* __restrict__ wb1,
                    const float* __restrict__ ws1,
                    const float* __restrict__ b1,
                    float* __restrict__ out, int n)
{
    __shared__ __align__(16) char smem[SMEM_SZ];
    const uint32_t sb = smem_u32(smem);
    float (*Hs)[HID + 1] = (float (*)[HID + 1])smem;    // [128][33] alias (post-GEMM)
    float* csc0T = (float*)(smem + PRM_OFF);            // [12][193]
    float* wb0s  = csc0T + 2316;
    float* csc1T = wb0s + 192;                          // [12][7]
    float* wb1s  = csc1T + 84;
    float* b0s   = wb1s + 6;
    float* mlpbs = b0s + 6;
    float* b1s   = mlpbs + 32;

    const int tid  = threadIdx.x;
    const int w    = tid >> 5;
    const int l    = tid & 31;
    const int row0 = blockIdx.x * RPB;
    const int toff = blockIdx.x % NTILES;     // tile-order stagger

    // ---- stage params ----
    for (int idx = tid; idx < NB * HID * W1; idx += NTHR) {
        int b = idx / (HID * W1), r = idx % (HID * W1);
        int i = r / W1, o = r % W1;
        csc0T[b * 193 + r] = coef0[i * (W1 * NB) + o * NB + b] * ws0[r];
    }
    for (int idx = tid; idx < HID * W1; idx += NTHR)
        wb0s[idx] = wb0[idx];
    if (tid < NB * 7) {
        int b = tid / 7, i = tid % 7;
        if (i < W1) csc1T[tid] = coef1[i * NB + b] * ws1[i];
    }
    if (tid < W1) { wb1s[tid] = wb1[tid]; b0s[tid] = b0[tid]; }
    if (tid < HID) mlpbs[tid] = mlp_b[tid];
    if (tid == 0) b1s[0] = b1[0];

    // ---- MMA geometry: warp w -> rows [w*32, w*32+32), all 32 cols ----
    float acc[2][4][4];
    #pragma unroll
    for (int mt = 0; mt < 2; mt++)
        #pragma unroll
        for (int nt = 0; nt < 4; nt++)
            #pragma unroll
            for (int q = 0; q < 4; q++) acc[mt][nt][q] = 0.0f;

    // ldmatrix lane coordinates
    const int g8 = l >> 3;
    const int r8 = l & 7;
    const uint32_t acolb = (uint32_t)((g8 >> 1) << 4);     // 0 or 16 bytes (k halves)
    const uint32_t aA = sb + AHI_OFF
                      + (uint32_t)((w << 5) + ((g8 & 1) << 3) + r8) * APA + acolb;
    const uint32_t bB = sb + BHI_OFF
                      + (uint32_t)(((g8 & 1) << 3) + r8) * APB + acolb;

    // staging coordinates
    const int ar = tid >> 2;         // A base row (0..31), rows ar + 32j
    const int ac = tid & 3;          // float4 col (0..3), 16 floats per row
    const int wr = tid >> 3;         // W k-row (0..15)
    const int wc = tid & 7;          // W float4 col (0..7)

    float4 pa[4];
    float4 pw;

    // prologue: prefetch tile toff
    {
        const int kc = toff * KC;
        #pragma unroll
        for (int j = 0; j < 4; j++) {
            int gr = row0 + ar + 32 * j;
            pa[j] = make_float4(0.f, 0.f, 0.f, 0.f);
            if (gr < n)
                pa[j] = *(const float4*)&node_rep[(size_t)gr * D_IN + kc + ac * 4];
        }
        pw = *(const float4*)&mlp_w[(size_t)(kc + wr) * HID + wc * 4];
    }

    int t = toff;
    for (int tt = 0; tt < NTILES; tt++) {
        __syncthreads();
        // ---- STS: split fp32 -> bf16 hi/lo ----
        #pragma unroll
        for (int j = 0; j < 4; j++) {
            const int R = ar + 32 * j;
            uint32_t h01, h23, l01, l23;
            split4(pa[j], h01, h23, l01, l23);
            *(uint2*)(smem + AHI_OFF + R * APA + ac * 8) = make_uint2(h01, h23);
            *(uint2*)(smem + ALO_OFF + R * APA + ac * 8) = make_uint2(l01, l23);
        }
        {
            uint32_t h01, h23, l01, l23;
            split4(pw, h01, h23, l01, l23);
            *(uint2*)(smem + BHI_OFF + wr * APB + wc * 8) = make_uint2(h01, h23);
            *(uint2*)(smem + BLO_OFF + wr * APB + wc * 8) = make_uint2(l01, l23);
        }
        __syncthreads();

        // ---- prefetch next tile in staggered order ----
        if (tt + 1 < NTILES) {
            int tn = t + 1; if (tn >= NTILES) tn = 0;
            const int kc = tn * KC;
            #pragma unroll
            for (int j = 0; j < 4; j++) {
                int gr = row0 + ar + 32 * j;
                float4 v = make_float4(0.f, 0.f, 0.f, 0.f);
                if (gr < n)
                    v = *(const float4*)&node_rep[(size_t)gr * D_IN + kc + ac * 4];
                pa[j] = v;
            }
            pw = *(const float4*)&mlp_w[(size_t)(kc + wr) * HID + wc * 4];
        }

        // ---- compute: 8 ldmatrix + 24 mma (k16) ----
        {
            uint32_t ah[2][4], al[2][4], bh[8], bl[8];
            LDSM4(ah[0][0], ah[0][1], ah[0][2], ah[0][3], aA);
            LDSM4(ah[1][0], ah[1][1], ah[1][2], ah[1][3], aA + 16 * APA);
            LDSM4(al[0][0], al[0][1], al[0][2], al[0][3], aA + ALO_OFF);
            LDSM4(al[1][0], al[1][1], al[1][2], al[1][3], aA + ALO_OFF + 16 * APA);
            LDSM4T(bh[0], bh[1], bh[2], bh[3], bB);
            LDSM4T(bh[4], bh[5], bh[6], bh[7], bB + 32);
            LDSM4T(bl[0], bl[1], bl[2], bl[3], bB + (BLO_OFF - BHI_OFF));
            LDSM4T(bl[4], bl[5], bl[6], bl[7], bB + (BLO_OFF - BHI_OFF) + 32);
            #pragma unroll
            for (int mt = 0; mt < 2; mt++)
                #pragma unroll
                for (int nt = 0; nt < 4; nt++) {
                    MMA16816(acc[mt][nt], ah[mt], bh[2 * nt], bh[2 * nt + 1]);
                    MMA16816(acc[mt][nt], ah[mt], bl[2 * nt], bl[2 * nt + 1]);
                    MMA16816(acc[mt][nt], al[mt], bh[2 * nt], bh[2 * nt + 1]);
                }
        }

        t++; if (t >= NTILES) t = 0;
    }
    __syncthreads();   // GEMM SMEM dead; overwrite with Hs

    // ---- epilogue: fragments -> Hs (+bias) ----
    {
        const int g = l >> 2, tq = l & 3;
        #pragma unroll
        for (int mt = 0; mt < 2; mt++) {
            const int R = w * 32 + mt * 16 + g;
            #pragma unroll
            for (int nt = 0; nt < 4; nt++) {
                const int C = nt * 8 + tq * 2;
                Hs[R    ][C    ] = acc[mt][nt][0] + mlpbs[C];
                Hs[R    ][C + 1] = acc[mt][nt][1] + mlpbs[C + 1];
                Hs[R + 8][C    ] = acc[mt][nt][2] + mlpbs[C];
                Hs[R + 8][C + 1] = acc[mt][nt][3] + mlpbs[C + 1];
            }
        }
    }
    __syncthreads();

    // ---- KAN: one thread per row ----
    {
        const int rr = tid;
        const int grow = row0 + rr;
        float acc6[W1] = {0.f, 0.f, 0.f, 0.f, 0.f, 0.f};
        #pragma unroll 1
        for (int i = 0; i < HID; i++) {
            float x = Hs[rr][i];
            float Bv[5]; int ix[5];
            basis5m(x, Bv, ix);
            float s = silu_f(x);
            const int base = i * W1;
            int a0 = ix[0] * 193 + base, a1 = ix[1] * 193 + base,
                a2 = ix[2] * 193 + base, a3 = ix[3] * 193 + base,
                a4 = ix[4] * 193 + base;
            #pragma unroll
            for (int o = 0; o < W1; o++) {
                float d =      Bv[0] * csc0T[a0 + o];
                d = fmaf(Bv[1], csc0T[a1 + o], d);
                d = fmaf(Bv[2], csc0T[a2 + o], d);
                d = fmaf(Bv[3], csc0T[a3 + o], d);
                d = fmaf(Bv[4], csc0T[a4 + o], d);
                acc6[o] = fmaf(s, wb0s[base + o], acc6[o] + d);
            }
        }
        float res = b1s[0];
        #pragma unroll 1
        for (int i = 0; i < W1; i++) {
            float x = acc6[i] + b0s[i];
            float Bv[5]; int ix[5];
            basis5m(x, Bv, ix);
            float d =      Bv[0] * csc1T[ix[0] * 7 + i];
            d = fmaf(Bv[1], csc1T[ix[1] * 7 + i], d);
            d = fmaf(Bv[2], csc1T[ix[2] * 7 + i], d);
            d = fmaf(Bv[3], csc1T[ix[3] * 7 + i], d);
            d = fmaf(Bv[4], csc1T[ix[4] * 7 + i], d);
            res += d + silu_f(x) * wb1s[i];
        }
        if (grow < n) out[grow] = res;
    }
}

extern "C" void kernel_launch(void* const* d_in, const int* in_sizes, int n_in,
                              void* d_out, int out_size) {
    const float* node_rep = (const float*)d_in[0];
    const float* mlp_w    = (const float*)d_in[1];
    const float* mlp_b    = (const float*)d_in[2];
    const float* coef0    = (const float*)d_in[3];
    const float* wb0      = (const float*)d_in[4];
    const float* ws0      = (const float*)d_in[5];
    const float* b0       = (const float*)d_in[6];
    const float* coef1    = (const float*)d_in[7];
    const float* wb1      = (const float*)d_in[8];
    const float* ws1      = (const float*)d_in[9];
    const float* b1       = (const float*)d_in[10];

    int n = out_size;                       // 300000 rows, one output each
    int grid = (n + RPB - 1) / RPB;
    kan_mma_kernel<<<grid, NTHR>>>(node_rep, mlp_w, mlp_b, coef0, wb0, ws0,
                                   b0, coef1, wb1, ws1, b1,
                                   (float*)d_out, n);
}